// round 16
// baseline (speedup 1.0000x reference)
#include <cuda_runtime.h>
#include <cuda_fp16.h>
#include <math.h>
#include <cstdint>

// ---------------------------------------------------------------------------
// Problem constants
// ---------------------------------------------------------------------------
#define B_   2
#define T_   1024
#define C_   2048
#define NCH  8
#define KLAT 32
#define NKV  4
#define NREP 4
#define D_   128

#define KV_SPLIT 8
#define SPLITS  9          // attn token-list splits: 16*9 = 144 blocks ~ 1 wave

// Scratch (device globals; allocation is forbidden)
__device__ float  g_q[B_ * T_ * C_];                 // 16 MB
__device__ float  g_k[B_ * NCH * KLAT * NKV * D_];   // 1 MB
__device__ float  g_v[B_ * NCH * KLAT * NKV * D_];   // 1 MB
__device__ float  g_part[2 * KV_SPLIT * 512 * 512];  // 16 MB split-K partials
__device__ int    g_list[B_ * NCH * T_];             // token lists per channel
__device__ int    g_cnt[B_ * NCH];
// Fragment-order fp16 operands
__device__ __half g_xA [B_ * T_ * C_];               // 8 MB
__device__ __half g_csA[B_ * NCH * KLAT * C_];       // 2 MB
__device__ __half g_yA [B_ * T_ * C_];               // 8 MB (written by attn2)
__device__ __half g_WqB[C_ * C_];                    // 8 MB
__device__ __half g_WkB[C_ * NKV * D_];              // 2 MB
__device__ __half g_WvB[C_ * NKV * D_];              // 2 MB
__device__ __half g_WoB[C_ * C_];                    // 8 MB

// ---------------------------------------------------------------------------
// Helpers
// ---------------------------------------------------------------------------
__device__ __forceinline__ uint32_t smem_u32(const void* p) {
    uint32_t a;
    asm("{ .reg .u64 t; cvta.to.shared.u64 t, %1; cvt.u32.u64 %0, t; }"
        : "=r"(a) : "l"(p));
    return a;
}

__device__ __forceinline__ uint32_t pack_h2(float a, float b) {
    __half2 h = __halves2half2(__float2half_rn(a), __float2half_rn(b));
    return *(uint32_t*)&h;
}

// ---------------------------------------------------------------------------
// Tiled reformat A: fp32 [M,K] row-major -> fp16 fragment order (m16n8k16).
// ---------------------------------------------------------------------------
__global__ void __launch_bounds__(256) reformat_A_tiled(
    const float* __restrict__ src, __half* __restrict__ dst, int K)
{
    __shared__ uint32_t su[4096];      // 16 KB = one A chunk
    const int tid = threadIdx.x;
    const int cB  = blockIdx.x;        // k-chunk (K/64)
    const int rb  = blockIdx.y;        // 128-row block
    const int nch = K >> 6;

    const float* s0 = src + (size_t)rb * 128 * K + cB * 64;
    #pragma unroll
    for (int j = 0; j < 8; j++) {
        int idx = tid + j * 256;                 // 2048 float4
        int row = idx >> 4, c4 = idx & 15;
        float4 v = *(const float4*)(s0 + (size_t)row * K + c4 * 4);
        int t = row >> 4, g8 = row & 7, rowbit = (row >> 3) & 1;
        int k4 = c4 * 4;
        int s  = k4 >> 4;
        int km = k4 & 15;
        int khi = km >> 3;
        int tig = (km & 7) >> 1;
        int uu  = (t * 4 + s) * 32 + g8 * 4 + tig;
        int slot = (khi << 1) | rowbit;
        su[uu * 4 + slot]       = pack_h2(v.x, v.y);
        su[(uu + 1) * 4 + slot] = pack_h2(v.z, v.w);
    }
    __syncthreads();
    uint4* dout = (uint4*)(dst + ((size_t)rb * nch + cB) * 8192);
    const uint4* sin = (const uint4*)su;
    #pragma unroll
    for (int j = 0; j < 4; j++)
        dout[tid + j * 256] = sin[tid + j * 256];
}

// ---------------------------------------------------------------------------
// Tiled reformat B: fp32 [K,N] row-major -> fp16 fragment order.
// ---------------------------------------------------------------------------
__global__ void __launch_bounds__(256) reformat_B_tiled(
    const float* __restrict__ src, __half* __restrict__ dst, int K, int N)
{
    __shared__ __half sh[64][136];     // 64 k x 128 n (+8 pad)
    const int tid = threadIdx.x;
    const int nslice = blockIdx.x;     // 128-n slice
    const int cB = blockIdx.y;         // k-chunk
    const int nch = K >> 6;
    const int nb = nslice >> 1, half = nslice & 1;
    const int n0 = nslice * 128;

    const float* s0 = src + (size_t)cB * 64 * N + n0;
    #pragma unroll
    for (int j = 0; j < 8; j++) {
        int idx = tid + j * 256;
        int kr = idx >> 5, c4 = idx & 31;
        float4 v = *(const float4*)(s0 + (size_t)kr * N + c4 * 4);
        __half2 h01 = __halves2half2(__float2half_rn(v.x), __float2half_rn(v.y));
        __half2 h23 = __halves2half2(__float2half_rn(v.z), __float2half_rn(v.w));
        *(__half2*)&sh[kr][c4 * 4]     = h01;
        *(__half2*)&sh[kr][c4 * 4 + 2] = h23;
    }
    __syncthreads();

    uint2* dout = (uint2*)(dst + (((size_t)nb * nch + cB) * 4096 +
                                  (size_t)half * 2048) * 4);
    #pragma unroll
    for (int j = 0; j < 8; j++) {
        int o = tid + j * 256;
        int lane2 = o & 31, grp = o >> 5;
        int s  = grp & 3;
        int ntl = grp >> 2;
        int g8 = lane2 >> 2, tig = lane2 & 3;
        int nl = ntl * 8 + g8;
        int kp = s * 16 + 2 * tig;
        uint32_t lo = (uint32_t)__half_as_ushort(sh[kp][nl]) |
                      ((uint32_t)__half_as_ushort(sh[kp + 1][nl]) << 16);
        uint32_t hi = (uint32_t)__half_as_ushort(sh[kp + 8][nl]) |
                      ((uint32_t)__half_as_ushort(sh[kp + 9][nl]) << 16);
        dout[o] = make_uint2(lo, hi);
    }
}

// ---------------------------------------------------------------------------
// fp16 mma.sync GEMM (fp32 accumulate), fragment-order operands.
// Block 128x128, 8 warps (2m x 4n), K-chunk 64, 3-stage cp.async, 2 CTA/SM.
// Optional second B operand (Bfrag2) selected when z >= half_z (merged K/V).
// ---------------------------------------------------------------------------
#define BM 128
#define BN 128
#define STAGES 3
#define A_BYTES (BM * 64 * 2)                  // 16384 per chunk
#define B_BYTES (BN * 64 * 2)                  // 16384 per chunk
#define STAGE_BYTES (A_BYTES + B_BYTES)        // 32768
#define GEMM_SMEM (STAGES * STAGE_BYTES)       // 98304

__global__ void __launch_bounds__(256, 2) mma_gemm_kernel(
    const __half* __restrict__ Afrag, const __half* __restrict__ Bfrag,
    const __half* __restrict__ Bfrag2, int half_z,
    float* __restrict__ Cout, int M, int N, int K, int k_len,
    const float* __restrict__ scale_ptr)
{
    extern __shared__ char smem[];
    const uint32_t s_base = smem_u32(smem);

    const int tid    = threadIdx.x;
    const int lane   = tid & 31;
    const int wid    = tid >> 5;
    const int warp_m = wid & 1;
    const int warp_n = wid >> 1;

    const int rb  = blockIdx.y;
    const int nb  = blockIdx.x;
    const int z   = blockIdx.z;
    const int zz  = (half_z && z >= half_z) ? z - half_z : z;
    const __half* BF = (half_z && z >= half_z) ? Bfrag2 : Bfrag;
    const int nchK = K >> 6;
    const int kc0 = zz * (k_len >> 6);
    const int nch = k_len >> 6;
    float* outp = Cout + (size_t)z * M * N;

    const __half* AC = Afrag + (size_t)rb * nchK * 8192;
    const __half* BC = BF + (size_t)(nb >> 1) * nchK * 16384
                          + (size_t)(nb & 1) * 8192;

    auto issue = [&](int chunk, int buf) {
        uint32_t sb = s_base + buf * STAGE_BYTES;
        const __half* ga = AC + (size_t)(kc0 + chunk) * 8192;
        const __half* gb = BC + (size_t)(kc0 + chunk) * 16384;
        #pragma unroll
        for (int j = 0; j < 4; j++)
            asm volatile("cp.async.cg.shared.global [%0], [%1], 16;"
                :: "r"(sb + (tid + j * 256) * 16), "l"(ga + (tid + j * 256) * 8));
        #pragma unroll
        for (int j = 0; j < 4; j++)
            asm volatile("cp.async.cg.shared.global [%0], [%1], 16;"
                :: "r"(sb + A_BYTES + (tid + j * 256) * 16),
                   "l"(gb + (tid + j * 256) * 8));
        asm volatile("cp.async.commit_group;" ::: "memory");
    };

    float acc[4][4][4];
    #pragma unroll
    for (int a = 0; a < 4; a++)
        #pragma unroll
        for (int b = 0; b < 4; b++)
            #pragma unroll
            for (int c = 0; c < 4; c++) acc[a][b][c] = 0.0f;

    const int npro = (STAGES - 1 < nch) ? (STAGES - 1) : nch;
    for (int p = 0; p < npro; p++) issue(p, p % STAGES);

    for (int i = 0; i < nch; i++) {
        asm volatile("cp.async.wait_group %0;" :: "n"(STAGES - 2) : "memory");
        __syncthreads();

        // Issue next chunk's loads FIRST so DMA overlaps this chunk's math.
        // Buffer (i+STAGES-1)%STAGES was fully consumed in iteration i-1;
        // the barrier above guarantees all warps are past it.
        if (i + STAGES - 1 < nch)
            issue(i + STAGES - 1, (i + STAGES - 1) % STAGES);

        const uint32_t ab = s_base + (i % STAGES) * STAGE_BYTES;
        const uint32_t bb = ab + A_BYTES;

        #pragma unroll
        for (int s = 0; s < 4; s++) {
            uint32_t areg[4][4];
            #pragma unroll
            for (int mt = 0; mt < 4; mt++) {
                int t = warp_m * 4 + mt;
                uint32_t addr = ab + ((t * 4 + s) * 32 + lane) * 16;
                asm volatile("ld.shared.v4.b32 {%0,%1,%2,%3}, [%4];"
                    : "=r"(areg[mt][0]), "=r"(areg[mt][1]),
                      "=r"(areg[mt][2]), "=r"(areg[mt][3])
                    : "r"(addr));
            }
            uint32_t breg[4][2];
            #pragma unroll
            for (int nt8 = 0; nt8 < 4; nt8++) {
                int nt = warp_n * 4 + nt8;
                uint32_t addr = bb + ((nt * 4 + s) * 32 + lane) * 8;
                asm volatile("ld.shared.v2.b32 {%0,%1}, [%2];"
                    : "=r"(breg[nt8][0]), "=r"(breg[nt8][1])
                    : "r"(addr));
            }
            #pragma unroll
            for (int mt = 0; mt < 4; mt++)
                #pragma unroll
                for (int nt8 = 0; nt8 < 4; nt8++)
                    asm volatile(
                        "mma.sync.aligned.m16n8k16.row.col.f32.f16.f16.f32 "
                        "{%0,%1,%2,%3}, {%4,%5,%6,%7}, {%8,%9}, {%0,%1,%2,%3};"
                        : "+f"(acc[mt][nt8][0]), "+f"(acc[mt][nt8][1]),
                          "+f"(acc[mt][nt8][2]), "+f"(acc[mt][nt8][3])
                        : "r"(areg[mt][0]), "r"(areg[mt][1]),
                          "r"(areg[mt][2]), "r"(areg[mt][3]),
                          "r"(breg[nt8][0]), "r"(breg[nt8][1]));
        }
    }

    // Epilogue
    float scale = 1.0f;
    if (scale_ptr) scale = tanhf(*scale_ptr);
    const int m0 = rb * BM, n0 = nb * BN;
    const int g = lane >> 2, tig = lane & 3;
    #pragma unroll
    for (int mt = 0; mt < 4; mt++) {
        int row = m0 + warp_m * 64 + mt * 16 + g;
        #pragma unroll
        for (int nt8 = 0; nt8 < 4; nt8++) {
            int col = n0 + warp_n * 32 + nt8 * 8 + 2 * tig;
            float2 v0, v1;
            v0.x = acc[mt][nt8][0] * scale; v0.y = acc[mt][nt8][1] * scale;
            v1.x = acc[mt][nt8][2] * scale; v1.y = acc[mt][nt8][3] * scale;
            *(float2*)(outp + (size_t)row * N + col) = v0;
            *(float2*)(outp + (size_t)(row + 8) * N + col) = v1;
        }
    }
}

// ---------------------------------------------------------------------------
// Fused deterministic split-K reduction for K and V:
//   kk[i] = sum_{z<8} part[z][i];  vv[i] = sum_{z>=8} part[z][i]
// ---------------------------------------------------------------------------
__global__ void __launch_bounds__(256) reduce_kv_kernel(
    const float* __restrict__ part, float* __restrict__ kk,
    float* __restrict__ vv, int n)
{
    int i = (blockIdx.x * 256 + threadIdx.x) * 4;
    if (i < n) {
        float4 s = *(const float4*)(part + i);
        #pragma unroll
        for (int zz = 1; zz < KV_SPLIT; zz++) {
            float4 p = *(const float4*)(part + (size_t)zz * n + i);
            s.x += p.x; s.y += p.y; s.z += p.z; s.w += p.w;
        }
        *(float4*)(kk + i) = s;
        float4 t = *(const float4*)(part + (size_t)KV_SPLIT * n + i);
        #pragma unroll
        for (int zz = 1; zz < KV_SPLIT; zz++) {
            float4 p = *(const float4*)(part + (size_t)(KV_SPLIT + zz) * n + i);
            t.x += p.x; t.y += p.y; t.z += p.z; t.w += p.w;
        }
        *(float4*)(vv + i) = t;
    }
}

// ---------------------------------------------------------------------------
// Build per-(batch,channel) token lists. Grid = B_, block = T_ threads.
// ---------------------------------------------------------------------------
__global__ void __launch_bounds__(T_) build_lists_kernel(
    const int* __restrict__ mask, int* __restrict__ list, int* __restrict__ cnt)
{
    __shared__ int scnt[NCH];
    const int b = blockIdx.x;
    if (threadIdx.x < NCH) scnt[threadIdx.x] = 0;
    __syncthreads();
    const int t = threadIdx.x;
    const int n = mask[b * T_ + t];
    const int pos = atomicAdd(&scnt[n], 1);
    list[(b * NCH + n) * T_ + pos] = t;
    __syncthreads();
    if (threadIdx.x < NCH) cnt[b * NCH + threadIdx.x] = scnt[threadIdx.x];
}

// ---------------------------------------------------------------------------
// Channel-grouped attention; writes yA DIRECTLY in fragment-A fp16 order.
// Block = (channel bn, split sp), 512 threads = 4 tokens x 4 kv-groups.
// ---------------------------------------------------------------------------
#define NSUB 4
#define KT_FLOATS (4 * 128 * 33)                       // 16896
#define VS_FLOATS (KLAT * 512)                         // 16384
#define QS_FLOATS (NSUB * 4 * NREP * D_)               // 8192
#define WS_FLOATS (NSUB * 4 * NREP * KLAT)             // 2048
#define ATTN_SMEM ((KT_FLOATS + VS_FLOATS + QS_FLOATS + WS_FLOATS) * 4)

__global__ void __launch_bounds__(512, 1) attn2_kernel(
    const float* __restrict__ q, const float* __restrict__ k,
    const float* __restrict__ v, __half* __restrict__ yA,
    const int* __restrict__ list, const int* __restrict__ cnt)
{
    extern __shared__ float sm[];
    float* Kt = sm;                                   // [g][d][key] pad 33
    float* Vs = Kt + KT_FLOATS;                       // [key][512]
    float* qs = Vs + VS_FLOATS;                       // [sub][g][512]
    float* ws = qs + QS_FLOATS;                       // [sub][g][r][32]

    const int bn   = blockIdx.x;                      // b*NCH + n
    const int b    = bn >> 3;
    const int sp   = blockIdx.y;
    const int tid  = threadIdx.x;
    const int wid  = tid >> 5;
    const int lane = tid & 31;
    const int sub  = wid >> 2;                        // 0..3
    const int g    = wid & 3;

    // Stage K (transposed) and V
    const float* kch = k + (size_t)bn * KLAT * 512;
    const float* vch = v + (size_t)bn * KLAT * 512;
    for (int idx = tid; idx < KLAT * 512; idx += 512) {
        int key = idx >> 9, col = idx & 511;
        Kt[((col >> 7) * 128 + (col & 127)) * 33 + key] = kch[idx];
        Vs[idx] = vch[idx];
    }
    __syncthreads();

    const int   cnt_bn = cnt[bn];
    const int*  lst    = list + bn * T_;
    const float scale  = 0.08838834764831845f;        // 1/sqrt(128)

    float* qs_w = qs + (sub * 4 + g) * (NREP * D_);
    float* ws_w = ws + (sub * 4 + g) * (NREP * KLAT);
    const float* ktg = Kt + g * 128 * 33;
    const float* vsg = Vs + g * D_;

    // Fragment coords that depend only on lane (d0 = lane*4)
    const int d0  = lane * 4;
    const int km  = d0 & 15;
    const int khi = km >> 3;
    const int tigA = (km & 7) >> 1;
    const int sA   = (d0 >> 4) & 3;

    for (int base = NSUB * sp; base < cnt_bn; base += NSUB * SPLITS) {
        const int ti = base + sub;
        if (ti >= cnt_bn) continue;
        const int t  = lst[ti];
        const int bt = b * T_ + t;

        // stage this token's q for group g (512 floats, 4 float4/lane)
        const float4* qsrc = (const float4*)(q + (size_t)bt * C_ + g * (NREP * D_));
        float4* qdst = (float4*)qs_w;
        #pragma unroll
        for (int i = 0; i < 4; i++) qdst[i * 32 + lane] = qsrc[i * 32 + lane];
        __syncwarp();

        // phase 1: lane = key; scores for 4 rep heads
        float s[NREP] = {0.f, 0.f, 0.f, 0.f};
        #pragma unroll 8
        for (int d4 = 0; d4 < D_; d4 += 4) {
            float kt0 = ktg[(d4 + 0) * 33 + lane];
            float kt1 = ktg[(d4 + 1) * 33 + lane];
            float kt2 = ktg[(d4 + 2) * 33 + lane];
            float kt3 = ktg[(d4 + 3) * 33 + lane];
            #pragma unroll
            for (int r = 0; r < NREP; r++) {
                const float4 qv = *(const float4*)(qs_w + r * D_ + d4);
                s[r] = fmaf(kt0, qv.x, s[r]);
                s[r] = fmaf(kt1, qv.y, s[r]);
                s[r] = fmaf(kt2, qv.z, s[r]);
                s[r] = fmaf(kt3, qv.w, s[r]);
            }
        }

        // phase 2: softmax over 32 keys
        #pragma unroll
        for (int r = 0; r < NREP; r++) {
            float sc = s[r] * scale;
            float m = sc;
            #pragma unroll
            for (int o = 16; o > 0; o >>= 1)
                m = fmaxf(m, __shfl_xor_sync(0xFFFFFFFFu, m, o));
            float e = expf(sc - m);
            float sum = e;
            #pragma unroll
            for (int o = 16; o > 0; o >>= 1)
                sum += __shfl_xor_sync(0xFFFFFFFFu, sum, o);
            ws_w[r * KLAT + lane] = e / sum;
        }
        __syncwarp();

        // phase 3: lane = d-chunk; accumulate over keys from smem V
        float4 acc[NREP];
        #pragma unroll
        for (int r = 0; r < NREP; r++) acc[r] = make_float4(0.f, 0.f, 0.f, 0.f);
        #pragma unroll 8
        for (int key = 0; key < KLAT; key++) {
            float4 vv = *(const float4*)(vsg + key * 512 + lane * 4);
            #pragma unroll
            for (int r = 0; r < NREP; r++) {
                float w = ws_w[r * KLAT + key];
                acc[r].x = fmaf(w, vv.x, acc[r].x);
                acc[r].y = fmaf(w, vv.y, acc[r].y);
                acc[r].z = fmaf(w, vv.z, acc[r].z);
                acc[r].w = fmaf(w, vv.w, acc[r].w);
            }
        }

        // write yA in fragment-A fp16 order
        const int rbA    = bt >> 7;
        const int tA     = (bt >> 4) & 7;
        const int g8A    = bt & 7;
        const int rowbit = (bt >> 3) & 1;
        const int slot   = (khi << 1) | rowbit;
        uint32_t* ybase = (uint32_t*)(yA + (size_t)rbA * 32 * 8192);
        #pragma unroll
        for (int r = 0; r < NREP; r++) {
            const int kglob = g * 512 + r * 128 + d0;
            const int c     = kglob >> 6;
            const int ul    = (tA * 4 + sA) * 32 + g8A * 4 + tigA;
            uint32_t* p = ybase + (size_t)c * 4096 + ul * 4 + slot;
            p[0] = pack_h2(acc[r].x, acc[r].y);
            p[4] = pack_h2(acc[r].z, acc[r].w);
        }
    }
}

// ---------------------------------------------------------------------------
// Launch. Inputs: x, channel_states, channel_mask, Wq, Wk, Wv, Wo, gate.
// ---------------------------------------------------------------------------
extern "C" void kernel_launch(void* const* d_in, const int* in_sizes, int n_in,
                              void* d_out, int out_size)
{
    const float* x    = (const float*)d_in[0];
    const float* cs   = (const float*)d_in[1];
    const int*   mask = (const int*)d_in[2];
    const float* Wq   = (const float*)d_in[3];
    const float* Wk   = (const float*)d_in[4];
    const float* Wv   = (const float*)d_in[5];
    const float* Wo   = (const float*)d_in[6];
    const float* gate = (const float*)d_in[7];
    float* out = (float*)d_out;

    float *q, *kk, *vv, *part;
    int *list, *cnt;
    __half *xA, *csA, *yA, *WqB, *WkB, *WvB, *WoB;
    cudaGetSymbolAddress((void**)&q,    g_q);
    cudaGetSymbolAddress((void**)&kk,   g_k);
    cudaGetSymbolAddress((void**)&vv,   g_v);
    cudaGetSymbolAddress((void**)&part, g_part);
    cudaGetSymbolAddress((void**)&list, g_list);
    cudaGetSymbolAddress((void**)&cnt,  g_cnt);
    cudaGetSymbolAddress((void**)&xA,   g_xA);
    cudaGetSymbolAddress((void**)&csA,  g_csA);
    cudaGetSymbolAddress((void**)&yA,   g_yA);
    cudaGetSymbolAddress((void**)&WqB,  g_WqB);
    cudaGetSymbolAddress((void**)&WkB,  g_WkB);
    cudaGetSymbolAddress((void**)&WvB,  g_WvB);
    cudaGetSymbolAddress((void**)&WoB,  g_WoB);

    cudaFuncSetAttribute(mma_gemm_kernel,
                         cudaFuncAttributeMaxDynamicSharedMemorySize, GEMM_SMEM);
    cudaFuncSetAttribute(attn2_kernel,
                         cudaFuncAttributeMaxDynamicSharedMemorySize, ATTN_SMEM);

    const int M1  = B_ * T_;          // 2048
    const int Mkv = B_ * NCH * KLAT;  // 512
    const int Nkv = NKV * D_;         // 512

    // idx 0-2: Q operands + lists. idx 3 = Q GEMM (ncu capture slot).
    reformat_A_tiled<<<dim3(C_ / 64, M1 / 128), 256>>>(x, xA, C_);       // 0
    reformat_B_tiled<<<dim3(C_ / 128, C_ / 64), 256>>>(Wq, WqB, C_, C_); // 1
    build_lists_kernel<<<B_, T_>>>(mask, list, cnt);                     // 2
    mma_gemm_kernel<<<dim3(C_ / BN, M1 / BM, 1), 256, GEMM_SMEM>>>(      // 3
        xA, WqB, nullptr, 0, q, M1, C_, C_, C_, nullptr);

    // K/V path: merged K+V split-K GEMM (z 0..7 = K, 8..15 = V)
    reformat_A_tiled<<<dim3(C_ / 64, Mkv / 128), 256>>>(cs, csA, C_);
    reformat_B_tiled<<<dim3(Nkv / 128, C_ / 64), 256>>>(Wk, WkB, C_, Nkv);
    reformat_B_tiled<<<dim3(Nkv / 128, C_ / 64), 256>>>(Wv, WvB, C_, Nkv);
    mma_gemm_kernel<<<dim3(Nkv / BN, Mkv / BM, 2 * KV_SPLIT), 256, GEMM_SMEM>>>(
        csA, WkB, WvB, KV_SPLIT, part, Mkv, Nkv, C_, C_ / KV_SPLIT, nullptr);
    reduce_kv_kernel<<<(Mkv * Nkv) / 1024, 256>>>(part, kk, vv, Mkv * Nkv);

    // Attention -> writes yA directly in fragment order
    attn2_kernel<<<dim3(B_ * NCH, SPLITS), 512, ATTN_SMEM>>>(
        q, kk, vv, yA, list, cnt);

    // Output projection + tanh(gate)
    reformat_B_tiled<<<dim3(C_ / 128, C_ / 64), 256>>>(Wo, WoB, C_, C_);
    mma_gemm_kernel<<<dim3(C_ / BN, M1 / BM, 1), 256, GEMM_SMEM>>>(
        yA, WoB, nullptr, 0, out, M1, C_, C_, C_, gate);
}